// round 1
// baseline (speedup 1.0000x reference)
#include <cuda_runtime.h>

// ExtractTensorPatches: x (4,32,256,256) f32 -> out (4,961,32,16,16) f32
// out[b,l,c,i,j] = x[b,c,oh*8+i,ow*8+j] + EPS * sum_{a,b'} x[b,c,oh*8+a,ow*8+b']
// where l = oh*31 + ow.

#define BATCH 4
#define CHAN  32
#define HW    256
#define WIN   16
#define STR   8
#define HO    31
#define WO    31
#define LPATCH (HO * WO)            // 961
#define OWG    8                    // ceil(31/4) ow-groups of 4 patches

__device__ __forceinline__ float4 ld4(const float* p) {
    return *reinterpret_cast<const float4*>(p);
}

__global__ __launch_bounds__(256)
void extract_patches_kernel(const float* __restrict__ x, float* __restrict__ out) {
    const float EPS = 1e-6f;

    int bx = blockIdx.x;
    int owg = bx & 7;                       // 0..7
    int oh  = (bx >> 3) % HO;               // 0..30
    int c   = (bx / (8 * HO)) & (CHAN - 1); // 0..31
    int b   = bx / (8 * HO * CHAN);         // 0..3

    int tid = threadIdx.x;
    int g   = tid >> 6;        // patch within block: 0..3
    int p   = tid & 63;        // lane within patch
    int i   = p >> 2;          // patch row 0..15
    int seg = p & 3;           // float4 segment within row (4 floats each)

    int ow = owg * 4 + g;
    bool valid = (ow < WO);

    float4 v = make_float4(0.f, 0.f, 0.f, 0.f);
    if (valid) {
        size_t src_off = ((size_t)(b * CHAN + c) * HW + (size_t)(oh * STR + i)) * HW
                         + (size_t)(ow * STR + seg * 4);
        v = ld4(x + src_off);
    }

    // per-thread partial sum of 4 elements
    float s = v.x + v.y + v.z + v.w;

    // warp reduce (each warp = 32 threads = half a patch)
    #pragma unroll
    for (int off = 16; off > 0; off >>= 1)
        s += __shfl_xor_sync(0xffffffffu, s, off);

    __shared__ float wsum[8];
    int wid = tid >> 5;
    if ((tid & 31) == 0) wsum[wid] = s;
    __syncthreads();

    if (valid) {
        float S = wsum[g * 2] + wsum[g * 2 + 1];   // full 256-elem patch sum
        float e = EPS * S;
        float4 o = make_float4(v.x + e, v.y + e, v.z + e, v.w + e);

        int l = oh * WO + ow;
        size_t dst_off = (((size_t)(b * LPATCH + l) * CHAN + c) * (WIN * WIN))
                         + (size_t)(i * WIN + seg * 4);
        *reinterpret_cast<float4*>(out + dst_off) = o;
    }
}

extern "C" void kernel_launch(void* const* d_in, const int* in_sizes, int n_in,
                              void* d_out, int out_size) {
    const float* x = (const float*)d_in[0];
    float* out = (float*)d_out;

    dim3 grid(BATCH * CHAN * HO * OWG);   // 31744
    dim3 block(256);
    extract_patches_kernel<<<grid, block>>>(x, out);
}

// round 2
// speedup vs baseline: 1.7441x; 1.7441x over previous
#include <cuda_runtime.h>

// ExtractTensorPatches: x (4,32,256,256) f32 -> out (4,961,32,16,16) f32
// out[b,l,c,i,j] = x[b,c,oh*8+i,ow*8+j] + EPS * patch_sum(b,c,oh,ow)
// l = oh*31 + ow.
//
// One CTA per (b,c,oh): loads 16x256 input row band into smem once,
// computes all 31 patch sums, streams out 31 patches of 256 floats.

#define CHAN   32
#define HW     256
#define WIN    16
#define STR    8
#define HO     31
#define WO     31
#define LPATCH (HO * WO)       // 961
#define TPAD   260             // 256 + 4 pad (keeps 16B alignment, shifts banks)

__device__ __forceinline__ float4 ld4g(const float* p) {
    return *reinterpret_cast<const float4*>(p);
}

__global__ __launch_bounds__(256)
void extract_patches_kernel(const float* __restrict__ x, float* __restrict__ out) {
    const float EPS = 1e-6f;

    __shared__ float tile[WIN][TPAD];     // 16 rows x 256 (+4 pad) floats
    __shared__ float part[64][4];         // per-(col4, row-group) partial sums
    __shared__ float colsum4[64];         // sum over 16 rows of each 4-col group
    __shared__ float psum[WO];            // 31 patch sums

    int bx = blockIdx.x;
    int oh = bx % HO;
    int c  = (bx / HO) & (CHAN - 1);
    int b  = bx / (HO * CHAN);

    int tid  = threadIdx.x;
    int wid  = tid >> 5;
    int lane = tid & 31;

    const float* src = x + ((size_t)(b * CHAN + c) * HW + (size_t)(oh * STR)) * HW;

    // ---- Phase 1: load 16x256 band (1024 float4s; 4 per thread), accumulate
    // per-thread partial sum. Thread covers fixed col4 = tid&63, rows r0+{0,4,8,12}.
    int col4 = tid & 63;
    int r0   = tid >> 6;
    float acc = 0.f;
    #pragma unroll
    for (int k = 0; k < 4; k++) {
        int r = r0 + 4 * k;
        float4 v = ld4g(src + (size_t)r * HW + col4 * 4);
        acc += v.x + v.y + v.z + v.w;
        *reinterpret_cast<float4*>(&tile[r][col4 * 4]) = v;
    }
    part[col4][r0] = acc;
    __syncthreads();

    // ---- Phase 2: column-group sums over all 16 rows (threads 0..63)
    if (tid < 64) {
        colsum4[tid] = part[tid][0] + part[tid][1] + part[tid][2] + part[tid][3];
    }
    __syncthreads();

    // ---- Phase 3: patch sums. Window = 16 cols = 4 consecutive 4-col groups
    // starting at group 2*ow. (threads 0..30)
    if (tid < WO) {
        int g0 = 2 * tid;
        psum[tid] = colsum4[g0] + colsum4[g0 + 1] + colsum4[g0 + 2] + colsum4[g0 + 3];
    }
    __syncthreads();

    // ---- Phase 4: write 31 patches. Warp w handles ow = w, w+8, ...
    // Each patch = 256 floats = 64 float4; lane does q=lane and q=lane+32.
    size_t out_base = (((size_t)b * LPATCH + (size_t)oh * WO) * CHAN + c) * (size_t)(WIN * WIN);
    for (int ow = wid; ow < WO; ow += 8) {
        float e = EPS * psum[ow];
        float* dst = out + out_base + (size_t)ow * (CHAN * WIN * WIN);
        #pragma unroll
        for (int h = 0; h < 2; h++) {
            int q   = lane + 32 * h;     // float4 index within patch, 0..63
            int i   = q >> 2;            // patch row
            int seg = q & 3;             // 4-float segment within row
            float4 v = *reinterpret_cast<const float4*>(&tile[i][ow * STR + seg * 4]);
            v.x += e; v.y += e; v.z += e; v.w += e;
            __stcs(reinterpret_cast<float4*>(dst + q * 4), v);
        }
    }
}

extern "C" void kernel_launch(void* const* d_in, const int* in_sizes, int n_in,
                              void* d_out, int out_size) {
    const float* x = (const float*)d_in[0];
    float* out = (float*)d_out;

    dim3 grid(4 * CHAN * HO);   // 3968 CTAs: one per (b, c, oh)
    dim3 block(256);
    extract_patches_kernel<<<grid, block>>>(x, out);
}

// round 3
// speedup vs baseline: 1.7462x; 1.0012x over previous
#include <cuda_runtime.h>

// ExtractTensorPatches: x (4,32,256,256) f32 -> out (4,961,32,16,16) f32
// out[b,l,c,i,j] = x[b,c,oh*8+i,ow*8+j] + EPS * patch_sum(b,c,oh,ow)
// l = oh*31 + ow.
//
// One CTA per (b,c,oh): loads 16x256 input row band into smem once,
// computes all 31 patch sums, streams out 31 patches of 256 floats.
// Row stride 272 (mod 32 = 16) makes LDS.128 quarter-warps conflict-free.

#define CHAN   32
#define HW     256
#define WIN    16
#define STR    8
#define HO     31
#define WO     31
#define LPATCH (HO * WO)       // 961
#define TPAD   272             // 256 + 16 pad: rows i/i+1 hit disjoint bank halves

__device__ __forceinline__ float4 ld4g(const float* p) {
    return *reinterpret_cast<const float4*>(p);
}

__global__ __launch_bounds__(256)
void extract_patches_kernel(const float* __restrict__ x, float* __restrict__ out) {
    const float EPS = 1e-6f;

    __shared__ float tile[WIN][TPAD];     // 16 rows x 256 (+16 pad) floats
    __shared__ float part[64][5];         // per-(col4, row-group) partials (pad 5)
    __shared__ float colsum4[64];         // sum over 16 rows of each 4-col group
    __shared__ float psum[WO + 1];        // 31 patch sums

    int bx = blockIdx.x;
    int oh = bx % HO;
    int c  = (bx / HO) & (CHAN - 1);
    int b  = bx / (HO * CHAN);

    int tid  = threadIdx.x;
    int wid  = tid >> 5;
    int lane = tid & 31;

    const float* src = x + ((size_t)(b * CHAN + c) * HW + (size_t)(oh * STR)) * HW;

    // ---- Phase 1: load 16x256 band (1024 float4s; 4 per thread), accumulate
    // per-thread partial sum. Thread covers fixed col4 = tid&63, rows r0+{0,4,8,12}.
    int col4 = tid & 63;
    int r0   = tid >> 6;
    float acc = 0.f;
    #pragma unroll
    for (int k = 0; k < 4; k++) {
        int r = r0 + 4 * k;
        float4 v = ld4g(src + (size_t)r * HW + col4 * 4);
        acc += v.x + v.y + v.z + v.w;
        *reinterpret_cast<float4*>(&tile[r][col4 * 4]) = v;
    }
    part[col4][r0] = acc;
    __syncthreads();

    // ---- Phase 2: column-group sums over all 16 rows (threads 0..63)
    if (tid < 64) {
        colsum4[tid] = part[tid][0] + part[tid][1] + part[tid][2] + part[tid][3];
    }
    __syncthreads();

    // ---- Phase 3: patch sums (threads 0..30): window = 4 consecutive 4-col
    // groups starting at group 2*ow.
    if (tid < WO) {
        int g0 = 2 * tid;
        psum[tid] = colsum4[g0] + colsum4[g0 + 1] + colsum4[g0 + 2] + colsum4[g0 + 3];
    }
    __syncthreads();

    // ---- Phase 4: 62 tasks (31 patches x 2 half-patches of 512B each),
    // flat-distributed over 8 warps for balance + MLP.
    size_t out_base = (((size_t)b * LPATCH + (size_t)oh * WO) * CHAN + c) * (size_t)(WIN * WIN);
    #pragma unroll
    for (int t = wid; t < 62; t += 8) {
        int p = t >> 1;            // patch ow
        int h = t & 1;             // half of patch
        int q = lane + 32 * h;     // float4 index within patch, 0..63
        int i = q >> 2;            // patch row
        int s = q & 3;             // 4-float segment within row

        float4 v = *reinterpret_cast<const float4*>(&tile[i][p * STR + s * 4]);
        float e = EPS * psum[p];
        v.x += e; v.y += e; v.z += e; v.w += e;

        float* dst = out + out_base + (size_t)p * (CHAN * WIN * WIN) + q * 4;
        __stcs(reinterpret_cast<float4*>(dst), v);
    }
}

extern "C" void kernel_launch(void* const* d_in, const int* in_sizes, int n_in,
                              void* d_out, int out_size) {
    const float* x = (const float*)d_in[0];
    float* out = (float*)d_out;

    dim3 grid(4 * CHAN * HO);   // 3968 CTAs: one per (b, c, oh)
    dim3 block(256);
    extract_patches_kernel<<<grid, block>>>(x, out);
}